// round 11
// baseline (speedup 1.0000x reference)
#include <cuda_runtime.h>
#include <math.h>
#include <stdint.h>

// ---------------- problem constants ----------------
#define BATCH 128
#define TLEN  300
#define LW    28
#define OUTN  28
#define SPN   7
#define EN    20
#define HN    256
#define WN    273          // T - L + 1
#define WOUT  245          // W - OUT
#define FIN   49           // L + 1 + E
#define BD    10           // distinct batch rows (b % 10)
#define MROWS (WN*BD)      // 2730

// output region boundaries (float32 elements, tuple order)
#define P0 878080          // prediction_values (245,128,28)
#define P1 1756160         // actual_values    (245,128,28)
#define P2 1759744         // holdout_prediction (128,28)
#define P3 2738176         // rnn_out (273,128,28)
#define P4 2741760         // hav (128,28)
#define P5 2745344         // hav_norm (128,28)

// ---------------- device scratch (no cudaMalloc allowed) ----------------
__device__ float g_Sfull[BATCH*307];
__device__ float g_levels[BATCH*TLEN];
__device__ float g_win[MROWS*FIN];
__device__ float g_Z[MROWS*1024];
__device__ float g_Z2[MROWS*1024];
__device__ float g_hA[MROWS*HN];
__device__ float g_hB[MROWS*HN];
__device__ float g_rnn[MROWS*OUTN];
__device__ unsigned g_prog[4*16];   // per (layer slot, cluster) progress

// ---------------- helpers ----------------
__device__ __forceinline__ uint32_t s2u(const void* p){
    uint32_t a;
    asm("{ .reg .u64 t; cvta.to.shared.u64 t, %1; cvt.u32.u64 %0, t; }"
        : "=r"(a) : "l"(p));
    return a;
}
__device__ __forceinline__ float fast_sigmoid(float z){
    return __fdividef(1.f, 1.f + __expf(-z));
}
__device__ __forceinline__ float fast_tanh(float x){
    float a = fminf(fmaxf(x, -15.f), 15.f);
    float e = __expf(2.f*a);
    return __fdividef(e - 1.f, e + 1.f);
}

// ---------------- ES (Holt-Winters) smoothing + progress reset -------------
__global__ void es_kernel(const float* __restrict__ x,
                          const float* __restrict__ alpha_raw,
                          const float* __restrict__ gamma_raw,
                          const float* __restrict__ init_seas)
{
    __shared__ float ring[BATCH*SPN];
    int b = threadIdx.x;
    if (b < 64) g_prog[b] = 0u;      // reset pipeline progress every run
    if (b >= BATCH) return;
    float a = 1.f/(1.f+expf(-alpha_raw[b]));
    float g = 1.f/(1.f+expf(-gamma_raw[b]));
    float s0 = 0.f;
    for (int k = 0; k < SPN; k++) {
        float s = expf(init_seas[b*SPN + k]);
        g_Sfull[b*307 + k] = s;
        ring[b*SPN + k] = s;
        if (k == 0) s0 = s;
    }
    g_Sfull[b*307 + 7] = s0;
    float level = x[b*TLEN] / s0;
    g_levels[b*TLEN] = level;
    for (int t = 1; t < TLEN; t++) {
        float xt = x[b*TLEN + t];
        int slot = t % SPN;
        float s = ring[b*SPN + slot];
        float lvl  = a*(xt/s) + (1.f - a)*level;
        float snew = g*(xt/lvl) + (1.f - g)*s;
        ring[b*SPN + slot] = snew;
        g_Sfull[b*307 + t + 7] = snew;
        level = lvl;
        g_levels[b*TLEN + t] = lvl;
    }
}

// ---------------- build window_input (10 distinct batch rows) ----------
__global__ void build_win(const float* __restrict__ x,
                          const float* __restrict__ cats,
                          const float* __restrict__ myp)
{
    int idx = blockIdx.x*blockDim.x + threadIdx.x;
    if (idx >= MROWS*FIN) return;
    int f  = idx % FIN;
    int r  = idx / FIN;
    int bb = r % BD;
    int w  = r / BD;
    float v;
    if (f < LW) {
        int tt = w + f;
        v = x[bb*TLEN + tt] / g_Sfull[bb*307 + tt] / g_levels[bb*TLEN + 27 + w];
    } else if (f < LW + EN) {
        v = cats[bb*EN + (f - LW)];
    } else {
        v = myp[0];
    }
    g_win[idx] = v;
}

// ---------------- generic SGEMM-NT (64x64, used for K=49 and N=28) ---------
template<int ACT>
__global__ void sgemm_nt(const float* __restrict__ A,
                         const float* __restrict__ Bm,
                         const float* __restrict__ bias,
                         float* __restrict__ C,
                         int M, int N, int K)
{
    __shared__ float As[16][64];
    __shared__ float Bs[16][64];
    const int tid = threadIdx.x;
    const int mBase = blockIdx.y * 64;
    const int nBase = blockIdx.x * 64;
    const int lr = tid >> 2;
    const int lk = (tid & 3) << 2;
    const int tx = tid & 15, ty = tid >> 4;
    float acc[4][4] = {};

    for (int k0 = 0; k0 < K; k0 += 16) {
        {
            const int m = mBase + lr;
            const int n = nBase + lr;
            #pragma unroll
            for (int i = 0; i < 4; i++) {
                int k = k0 + lk + i;
                As[lk+i][lr] = (m < M && k < K) ? A[m*K + k] : 0.f;
                Bs[lk+i][lr] = (n < N && k < K) ? Bm[n*K + k] : 0.f;
            }
        }
        __syncthreads();
        #pragma unroll
        for (int kk = 0; kk < 16; kk++) {
            const float4 a4 = *(const float4*)&As[kk][ty << 2];
            const float4 b4 = *(const float4*)&Bs[kk][tx << 2];
            float av[4] = {a4.x, a4.y, a4.z, a4.w};
            float bv[4] = {b4.x, b4.y, b4.z, b4.w};
            #pragma unroll
            for (int i = 0; i < 4; i++)
                #pragma unroll
                for (int j = 0; j < 4; j++)
                    acc[i][j] += av[i] * bv[j];
        }
        __syncthreads();
    }

    #pragma unroll
    for (int i = 0; i < 4; i++) {
        int m = mBase + (ty << 2) + i;
        if (m >= M) continue;
        #pragma unroll
        for (int j = 0; j < 4; j++) {
            int n = nBase + (tx << 2) + j;
            if (n >= N) continue;
            float v = acc[i][j] + bias[n];
            if (ACT == 1) v = tanhf(v);
            C[m*N + n] = v;
        }
    }
}

// ================== fused: recurrence cluster + progressive consumer GEMM ===
// blockIdx < NCL*8  : lstm recurrence (identical to round-10 lstm_chain) plus
//                     per-interval progress publication (fence.gpu + relaxed
//                     store of it+1 by cluster rank0/tid0 after barrier wait).
// blockIdx >= NCL*8 : 128x128 tile GEMM C = act(bias + A(+R) @ Bm^T); tiles
//                     claimed m-major; each tile spin-waits (acquire+nanosleep)
//                     until ALL rec clusters published enough intervals to
//                     cover its A rows. A is the h buffer being produced.
template<int CPC, int D, int NCL, int ACT, int RES>
__global__ void __launch_bounds__(256,1) __cluster_dims__(8,1,1)
fused_rec_gemm(const float* __restrict__ Z,
               const float* __restrict__ Whh,
               float* __restrict__ h,
               const float* __restrict__ Agm,
               const float* __restrict__ Rgm,
               const float* __restrict__ Bgm,
               const float* __restrict__ bias,
               float* __restrict__ Cgm,
               int M, int N, int K, int progSlot)
{
    __shared__ __align__(16) float stage[2][CPC][256];  // rec parity buffer
    __shared__ float As[8][132];                         // gemm tiles
    __shared__ float Bs[8][132];

    const int tid = threadIdx.x;

    if (blockIdx.x < NCL*8) {
        // ======================= recurrence path ===========================
        uint32_t rank;
        asm("mov.u32 %0, %%cluster_ctarank;" : "=r"(rank));
        const int U0 = (int)rank * 32;
        const int kp = tid & 1;
        const int g  = (tid >> 1) & 3;
        const int ul = tid >> 3;
        const int clIdx = blockIdx.x >> 3;
        const int chBase = clIdx * CPC;

        ulonglong2 w[32];
        {
            const ulonglong2* w16 =
                (const ulonglong2*)(Whh + (g*HN + U0 + ul)*HN + kp*128);
            #pragma unroll
            for (int i = 0; i < 32; i++) w[i] = w16[i];
        }

        for (int i = tid; i < 2*CPC*256; i += 256) ((float*)stage)[i] = 0.f;
        __syncthreads();
        asm volatile("barrier.cluster.arrive.aligned;" ::: "memory");
        asm volatile("barrier.cluster.wait.aligned;"   ::: "memory");

        const uint32_t stageAddr = s2u(&stage[0][0][0]);
        uint32_t rstage[8];
        #pragma unroll
        for (int rk = 0; rk < 8; rk++)
            asm("mapa.shared::cluster.u32 %0, %1, %2;"
                : "=r"(rstage[rk]) : "r"(stageAddr), "r"(rk));

        const int lane = tid & 31;
        const int gbase = lane & ~7;
        const bool leader = ((lane & 7) == 0);
        float cst[CPC];
        #pragma unroll
        for (int j = 0; j < CPC; j++) cst[j] = 0.f;

        const int nIter = (WN + D - 1) / D;

        float zv[CPC];
        #pragma unroll
        for (int j = 0; j < CPC; j++) {
            const int ch = chBase + j;
            const int t = (ch % D);
            zv[j] = (kp == 0 && t < WN)
                  ? Z[(t*BD + ch/D)*1024 + g*HN + U0 + ul] : 0.f;
        }

        for (int it = 0; it < nIter; it++) {
            const int rp = (it + 1) & 1;
            const int wp = it & 1;

            #pragma unroll
            for (int j = 0; j < CPC; j++) {
                const int ch  = chBase + j;
                const int row = ch / D;
                const int t   = it*D + (ch % D);
                const ulonglong2* hp = (const ulonglong2*)&stage[rp][j][kp*128];
                unsigned long long p0a=0ull, p0b=0ull, p1a=0ull, p1b=0ull;
                #pragma unroll
                for (int i = 0; i < 32; i += 2) {
                    ulonglong2 h0 = hp[i];
                    ulonglong2 h1 = hp[i+1];
                    asm("fma.rn.f32x2 %0, %1, %2, %0;" : "+l"(p0a) : "l"(w[i].x),   "l"(h0.x));
                    asm("fma.rn.f32x2 %0, %1, %2, %0;" : "+l"(p1a) : "l"(w[i].y),   "l"(h0.y));
                    asm("fma.rn.f32x2 %0, %1, %2, %0;" : "+l"(p0b) : "l"(w[i+1].x), "l"(h1.x));
                    asm("fma.rn.f32x2 %0, %1, %2, %0;" : "+l"(p1b) : "l"(w[i+1].y), "l"(h1.y));
                }
                float v = __uint_as_float((unsigned)p0a) + __uint_as_float((unsigned)(p0a>>32))
                        + __uint_as_float((unsigned)p0b) + __uint_as_float((unsigned)(p0b>>32))
                        + __uint_as_float((unsigned)p1a) + __uint_as_float((unsigned)(p1a>>32))
                        + __uint_as_float((unsigned)p1b) + __uint_as_float((unsigned)(p1b>>32));
                v += __shfl_xor_sync(0xffffffffu, v, 1);
                if (kp == 0) v += zv[j];
                float zi = __shfl_sync(0xffffffffu, v, gbase + 0);
                float zf = __shfl_sync(0xffffffffu, v, gbase + 2);
                float zg = __shfl_sync(0xffffffffu, v, gbase + 4);
                float zo = __shfl_sync(0xffffffffu, v, gbase + 6);
                if (leader && t < WN) {
                    float ig = fast_sigmoid(zi);
                    float fg = fast_sigmoid(zf);
                    float og = fast_sigmoid(zo);
                    float cn = fg*cst[j] + ig*fast_tanh(zg);
                    cst[j] = cn;
                    float hn = og*fast_tanh(cn);
                    h[(t*BD + row)*HN + U0 + ul] = hn;
                    uint32_t off = ((wp*CPC + j)*256 + U0 + ul)*4;
                    unsigned hu = __float_as_uint(hn);
                    #pragma unroll
                    for (int rk = 0; rk < 8; rk++)
                        asm volatile("st.shared::cluster.b32 [%0], %1;"
                                     :: "r"(rstage[rk] + off), "r"(hu) : "memory");
                }
            }

            asm volatile("barrier.cluster.arrive.aligned;" ::: "memory");

            #pragma unroll
            for (int j = 0; j < CPC; j++) {
                const int ch = chBase + j;
                const int t = (it+1)*D + (ch % D);
                zv[j] = (kp == 0 && t < WN && it+1 < nIter)
                      ? Z[(t*BD + ch/D)*1024 + g*HN + U0 + ul] : 0.f;
            }

            asm volatile("barrier.cluster.wait.aligned;" ::: "memory");

            // publish: all leaders' h stores for interval `it` happen-before
            // this point via the cluster barrier; fence raises to gpu scope.
            if (rank == 0 && tid == 0) {
                asm volatile("fence.acq_rel.gpu;" ::: "memory");
                asm volatile("st.relaxed.gpu.global.u32 [%0], %1;"
                             :: "l"(&g_prog[progSlot*16 + clIdx]),
                                "r"((unsigned)(it+1)) : "memory");
            }
        }
        return;
    }

    // ========================= consumer GEMM path ===========================
    const int nG   = (int)gridDim.x - NCL*8;
    const int gIdx = (int)blockIdx.x - NCL*8;
    const int MT = (M + 127)/128, NT = N/128;
    const int tx = tid & 15, ty = tid >> 4;
    const int lrow = tid >> 1;
    const int lhalf = (tid & 1) * 4;

    for (int tau = gIdx; tau < MT*NT; tau += nG) {
        const int mt = tau / NT, nt = tau % NT;
        // wait until all rec clusters have covered this tile's A rows
        {
            int lastRow = mt*128 + 127; if (lastRow > M-1) lastRow = M-1;
            unsigned target = (unsigned)((lastRow / BD) / D + 1);
            for (int cl = 0; cl < NCL; cl++) {
                const unsigned* pp = &g_prog[progSlot*16 + cl];
                unsigned v;
                while (true) {
                    asm volatile("ld.acquire.gpu.global.u32 %0, [%1];"
                                 : "=r"(v) : "l"(pp) : "memory");
                    if (v >= target) break;
                    __nanosleep(128);
                }
            }
        }
        const int mBase = mt*128, nBase = nt*128;
        float acc[8][8] = {};
        for (int k0 = 0; k0 < K; k0 += 8) {
            {
                int m = mBase + lrow;
                float4 v = make_float4(0.f,0.f,0.f,0.f);
                if (m < M) {
                    v = *(const float4*)&Agm[m*K + k0 + lhalf];
                    if (RES) {
                        float4 rv = *(const float4*)&Rgm[m*K + k0 + lhalf];
                        v.x += rv.x; v.y += rv.y; v.z += rv.z; v.w += rv.w;
                    }
                }
                As[lhalf+0][lrow] = v.x; As[lhalf+1][lrow] = v.y;
                As[lhalf+2][lrow] = v.z; As[lhalf+3][lrow] = v.w;
                int n = nBase + lrow;
                float4 wv = (n < N) ? *(const float4*)&Bgm[n*K + k0 + lhalf]
                                    : make_float4(0.f,0.f,0.f,0.f);
                Bs[lhalf+0][lrow] = wv.x; Bs[lhalf+1][lrow] = wv.y;
                Bs[lhalf+2][lrow] = wv.z; Bs[lhalf+3][lrow] = wv.w;
            }
            __syncthreads();
            #pragma unroll
            for (int kk = 0; kk < 8; kk++) {
                float a[8], b[8];
                *(float4*)&a[0] = *(const float4*)&As[kk][ty*8];
                *(float4*)&a[4] = *(const float4*)&As[kk][ty*8+4];
                *(float4*)&b[0] = *(const float4*)&Bs[kk][tx*8];
                *(float4*)&b[4] = *(const float4*)&Bs[kk][tx*8+4];
                #pragma unroll
                for (int i = 0; i < 8; i++)
                    #pragma unroll
                    for (int j = 0; j < 8; j++)
                        acc[i][j] = fmaf(a[i], b[j], acc[i][j]);
            }
            __syncthreads();
        }
        #pragma unroll
        for (int i = 0; i < 8; i++) {
            int m = mBase + ty*8 + i;
            if (m >= M) continue;
            #pragma unroll
            for (int j = 0; j < 8; j++) {
                int n = nBase + tx*8 + j;
                if (n >= N) continue;
                float v = acc[i][j] + bias[n];
                if (ACT == 1) v = tanhf(v);
                Cgm[m*N + n] = v;
            }
        }
    }
}

// ---------------- assemble all six outputs ----------------------------------
__global__ void outputs_kernel(const float* __restrict__ x,
                               const float* __restrict__ val,
                               float* __restrict__ out, int out_size)
{
    for (int idx = blockIdx.x*blockDim.x + threadIdx.x; idx < out_size;
         idx += gridDim.x*blockDim.x)
    {
        float v = 0.f;
        if (idx < P0) {                              // prediction_values
            int w = idx / 3584; int rem = idx - w*3584;
            int b = rem / 28;   int j = rem - b*28;
            v = g_rnn[(w*BD + (b % BD))*OUTN + j];
        } else if (idx < P1) {                       // actual_values
            int i = idx - P0;
            int wo = i / 3584; int rem = i - wo*3584;
            int b = rem / 28;  int j = rem - b*28;
            int tt = 28 + wo + j;
            v = x[b*TLEN + tt] / g_Sfull[b*307 + tt] / g_levels[b*TLEN + 27 + wo];
        } else if (idx < P2) {                       // holdout_prediction
            int i = idx - P1;
            int b = i / 28; int j = i - b*28;
            int k = 286 + j; if (k >= 307) k -= 7;
            float hh = g_rnn[(272*BD + (b % BD))*OUTN + j]
                       * g_Sfull[b*307 + k] * g_levels[b*TLEN + 299];
            v = hh > 0.f ? hh : 0.f;
        } else if (idx < P3) {                       // rnn_out
            int i = idx - P2;
            int w = i / 3584; int rem = i - w*3584;
            int b = rem / 28; int j = rem - b*28;
            v = g_rnn[(w*BD + (b % BD))*OUTN + j];
        } else if (idx < P4) {                       // hav
            v = val[idx - P3];
        } else if (idx < P5) {                       // hav_norm
            int i = idx - P4;
            int b = i / 28; int j = i - b*28;
            int k = 286 + j; if (k >= 307) k -= 7;
            v = val[b*28 + j] / g_Sfull[b*307 + k] / g_levels[b*TLEN + 299];
        }
        out[idx] = v;
    }
}

// ---------------- host launcher ----------------------------------------------
extern "C" void kernel_launch(void* const* d_in, const int* in_sizes, int n_in,
                              void* d_out, int out_size)
{
    const float* x      = (const float*)d_in[0];
    const float* val    = (const float*)d_in[1];
    const float* alpha  = (const float*)d_in[2];
    const float* gamma  = (const float*)d_in[3];
    const float* iseas  = (const float*)d_in[4];
    const float* cats   = (const float*)d_in[5];
    const float* myp    = (const float*)d_in[6];
    const float* Wih1   = (const float*)d_in[7];
    const float* Whh1   = (const float*)d_in[8];
    const float* b1     = (const float*)d_in[9];
    const float* Wih2   = (const float*)d_in[10];
    const float* Whh2   = (const float*)d_in[11];
    const float* b2     = (const float*)d_in[12];
    const float* Wih3   = (const float*)d_in[13];
    const float* Whh3   = (const float*)d_in[14];
    const float* b3     = (const float*)d_in[15];
    const float* Wih4   = (const float*)d_in[16];
    const float* Whh4   = (const float*)d_in[17];
    const float* b4     = (const float*)d_in[18];
    const float* lW     = (const float*)d_in[19];
    const float* lb     = (const float*)d_in[20];
    const float* sW     = (const float*)d_in[21];
    const float* sb     = (const float*)d_in[22];

    float *pWin, *pZ, *pZ2, *pHA, *pHB, *pRnn;
    cudaGetSymbolAddress((void**)&pWin, g_win);
    cudaGetSymbolAddress((void**)&pZ,   g_Z);
    cudaGetSymbolAddress((void**)&pZ2,  g_Z2);
    cudaGetSymbolAddress((void**)&pHA,  g_hA);
    cudaGetSymbolAddress((void**)&pHB,  g_hB);
    cudaGetSymbolAddress((void**)&pRnn, g_rnn);

    // 1) exponential smoothing + seasonals (+ progress reset)
    es_kernel<<<1, 128>>>(x, alpha, gamma, iseas);

    // 2) normalized window inputs
    build_win<<<(MROWS*FIN + 255)/256, 256>>>(x, cats, myp);

    // 3) layer-1 input GEMM (K=49) -> Z_A
    sgemm_nt<0><<<dim3(16, (MROWS+63)/64), 256>>>(pWin, Wih1, b1, pZ, MROWS, 1024, FIN);

    // 4) fused pipeline: rec(L) || input-GEMM(L+1) consuming h(L) progressively
    // fused1: rec1 (Z_A -> hA) || gemm2 (hA @ Wih2 -> Z_B)
    fused_rec_gemm<1,1,10,0,0><<<144, 256>>>(
        pZ, Whh1, pHA, pHA, nullptr, Wih2, b2, pZ2, MROWS, 1024, HN, 0);

    // fused2: rec2 (Z_B -> hB) || gemm3 (hB @ Wih3 -> Z_A)
    fused_rec_gemm<2,2,10,0,0><<<144, 256>>>(
        pZ2, Whh2, pHB, pHB, nullptr, Wih3, b3, pZ, MROWS, 1024, HN, 1);

    // fused3: rec3 (Z_A -> hA) || gemm4 (hA @ Wih4 -> Z_B)
    fused_rec_gemm<2,2,10,0,0><<<144, 256>>>(
        pZ, Whh3, pHA, pHA, nullptr, Wih4, b4, pZ2, MROWS, 1024, HN, 2);

    // fused4: rec4 (Z_B -> hA) || linear: tanh((hA+hB) @ lW^T + lb) -> Z_A
    fused_rec_gemm<4,6,15,1,1><<<144, 256>>>(
        pZ2, Whh4, pHA, pHA, pHB, lW, lb, pZ, MROWS, HN, HN, 3);

    // 5) score
    sgemm_nt<0><<<dim3(1, (MROWS+63)/64), 256>>>(pZ, sW, sb, pRnn, MROWS, OUTN, HN);

    // 6) outputs
    outputs_kernel<<<1024, 256>>>(x, val, (float*)d_out, out_size);
}

// round 12
// speedup vs baseline: 1.0282x; 1.0282x over previous
#include <cuda_runtime.h>
#include <math.h>
#include <stdint.h>

// ---------------- problem constants ----------------
#define BATCH 128
#define TLEN  300
#define LW    28
#define OUTN  28
#define SPN   7
#define EN    20
#define HN    256
#define WN    273          // T - L + 1
#define WOUT  245          // W - OUT
#define FIN   49           // L + 1 + E
#define BD    10           // distinct batch rows (b % 10)
#define MROWS (WN*BD)      // 2730
#define PUBK  16           // progress publish granularity (intervals)

// output region boundaries (float32 elements, tuple order)
#define P0 878080          // prediction_values (245,128,28)
#define P1 1756160         // actual_values    (245,128,28)
#define P2 1759744         // holdout_prediction (128,28)
#define P3 2738176         // rnn_out (273,128,28)
#define P4 2741760         // hav (128,28)
#define P5 2745344         // hav_norm (128,28)

// ---------------- device scratch (no cudaMalloc allowed) ----------------
__device__ float g_Sfull[BATCH*307];
__device__ float g_levels[BATCH*TLEN];
__device__ float g_win[MROWS*FIN];
__device__ float g_Z[MROWS*1024];
__device__ float g_Z2[MROWS*1024];
__device__ float g_hA[MROWS*HN];
__device__ float g_hB[MROWS*HN];
__device__ float g_rnn[MROWS*OUTN];
__device__ unsigned g_prog[4*16];   // per (layer slot, cluster) progress

// ---------------- helpers ----------------
__device__ __forceinline__ uint32_t s2u(const void* p){
    uint32_t a;
    asm("{ .reg .u64 t; cvta.to.shared.u64 t, %1; cvt.u32.u64 %0, t; }"
        : "=r"(a) : "l"(p));
    return a;
}
__device__ __forceinline__ float fast_sigmoid(float z){
    return __fdividef(1.f, 1.f + __expf(-z));
}
__device__ __forceinline__ float fast_tanh(float x){
    float a = fminf(fmaxf(x, -15.f), 15.f);
    float e = __expf(2.f*a);
    return __fdividef(e - 1.f, e + 1.f);
}

// ---------------- ES (Holt-Winters) smoothing + progress reset -------------
__global__ void es_kernel(const float* __restrict__ x,
                          const float* __restrict__ alpha_raw,
                          const float* __restrict__ gamma_raw,
                          const float* __restrict__ init_seas)
{
    __shared__ float ring[BATCH*SPN];
    int b = threadIdx.x;
    if (b < 64) g_prog[b] = 0u;      // reset pipeline progress every run
    if (b >= BATCH) return;
    float a = 1.f/(1.f+expf(-alpha_raw[b]));
    float g = 1.f/(1.f+expf(-gamma_raw[b]));
    float s0 = 0.f;
    for (int k = 0; k < SPN; k++) {
        float s = expf(init_seas[b*SPN + k]);
        g_Sfull[b*307 + k] = s;
        ring[b*SPN + k] = s;
        if (k == 0) s0 = s;
    }
    g_Sfull[b*307 + 7] = s0;
    float level = x[b*TLEN] / s0;
    g_levels[b*TLEN] = level;
    for (int t = 1; t < TLEN; t++) {
        float xt = x[b*TLEN + t];
        int slot = t % SPN;
        float s = ring[b*SPN + slot];
        float lvl  = a*(xt/s) + (1.f - a)*level;
        float snew = g*(xt/lvl) + (1.f - g)*s;
        ring[b*SPN + slot] = snew;
        g_Sfull[b*307 + t + 7] = snew;
        level = lvl;
        g_levels[b*TLEN + t] = lvl;
    }
}

// ---------------- build window_input (10 distinct batch rows) ----------
__global__ void build_win(const float* __restrict__ x,
                          const float* __restrict__ cats,
                          const float* __restrict__ myp)
{
    int idx = blockIdx.x*blockDim.x + threadIdx.x;
    if (idx >= MROWS*FIN) return;
    int f  = idx % FIN;
    int r  = idx / FIN;
    int bb = r % BD;
    int w  = r / BD;
    float v;
    if (f < LW) {
        int tt = w + f;
        v = x[bb*TLEN + tt] / g_Sfull[bb*307 + tt] / g_levels[bb*TLEN + 27 + w];
    } else if (f < LW + EN) {
        v = cats[bb*EN + (f - LW)];
    } else {
        v = myp[0];
    }
    g_win[idx] = v;
}

// ---------------- generic SGEMM-NT (64x64, used for K=49 and N=28) ---------
template<int ACT>
__global__ void sgemm_nt(const float* __restrict__ A,
                         const float* __restrict__ Bm,
                         const float* __restrict__ bias,
                         float* __restrict__ C,
                         int M, int N, int K)
{
    __shared__ float As[16][64];
    __shared__ float Bs[16][64];
    const int tid = threadIdx.x;
    const int mBase = blockIdx.y * 64;
    const int nBase = blockIdx.x * 64;
    const int lr = tid >> 2;
    const int lk = (tid & 3) << 2;
    const int tx = tid & 15, ty = tid >> 4;
    float acc[4][4] = {};

    for (int k0 = 0; k0 < K; k0 += 16) {
        {
            const int m = mBase + lr;
            const int n = nBase + lr;
            #pragma unroll
            for (int i = 0; i < 4; i++) {
                int k = k0 + lk + i;
                As[lk+i][lr] = (m < M && k < K) ? A[m*K + k] : 0.f;
                Bs[lk+i][lr] = (n < N && k < K) ? Bm[n*K + k] : 0.f;
            }
        }
        __syncthreads();
        #pragma unroll
        for (int kk = 0; kk < 16; kk++) {
            const float4 a4 = *(const float4*)&As[kk][ty << 2];
            const float4 b4 = *(const float4*)&Bs[kk][tx << 2];
            float av[4] = {a4.x, a4.y, a4.z, a4.w};
            float bv[4] = {b4.x, b4.y, b4.z, b4.w};
            #pragma unroll
            for (int i = 0; i < 4; i++)
                #pragma unroll
                for (int j = 0; j < 4; j++)
                    acc[i][j] += av[i] * bv[j];
        }
        __syncthreads();
    }

    #pragma unroll
    for (int i = 0; i < 4; i++) {
        int m = mBase + (ty << 2) + i;
        if (m >= M) continue;
        #pragma unroll
        for (int j = 0; j < 4; j++) {
            int n = nBase + (tx << 2) + j;
            if (n >= N) continue;
            float v = acc[i][j] + bias[n];
            if (ACT == 1) v = tanhf(v);
            C[m*N + n] = v;
        }
    }
}

// ================== fused: recurrence cluster + progressive consumer GEMM ===
// blockIdx < NCL*8  : lstm recurrence (round-10 lstm_chain) + COARSE progress
//                     publication: every PUBK intervals (and at the end),
//                     cluster rank0/tid0 does fence.acq_rel.gpu + relaxed
//                     store of it+1. ~18 fences/layer instead of 273.
// blockIdx >= NCL*8 : 128x128 tile GEMM C = act(bias + A(+R) @ Bm^T); tiles
//                     claimed m-major; each tile spin-waits (acquire +
//                     nanosleep) until ALL rec clusters covered its A rows.
template<int CPC, int D, int NCL, int ACT, int RES>
__global__ void __launch_bounds__(256,1) __cluster_dims__(8,1,1)
fused_rec_gemm(const float* __restrict__ Z,
               const float* __restrict__ Whh,
               float* __restrict__ h,
               const float* __restrict__ Agm,
               const float* __restrict__ Rgm,
               const float* __restrict__ Bgm,
               const float* __restrict__ bias,
               float* __restrict__ Cgm,
               int M, int N, int K, int progSlot)
{
    __shared__ __align__(16) float stage[2][CPC][256];  // rec parity buffer
    __shared__ float As[8][132];                         // gemm tiles
    __shared__ float Bs[8][132];

    const int tid = threadIdx.x;

    if (blockIdx.x < NCL*8) {
        // ======================= recurrence path ===========================
        uint32_t rank;
        asm("mov.u32 %0, %%cluster_ctarank;" : "=r"(rank));
        const int U0 = (int)rank * 32;
        const int kp = tid & 1;
        const int g  = (tid >> 1) & 3;
        const int ul = tid >> 3;
        const int clIdx = blockIdx.x >> 3;
        const int chBase = clIdx * CPC;

        ulonglong2 w[32];
        {
            const ulonglong2* w16 =
                (const ulonglong2*)(Whh + (g*HN + U0 + ul)*HN + kp*128);
            #pragma unroll
            for (int i = 0; i < 32; i++) w[i] = w16[i];
        }

        for (int i = tid; i < 2*CPC*256; i += 256) ((float*)stage)[i] = 0.f;
        __syncthreads();
        asm volatile("barrier.cluster.arrive.aligned;" ::: "memory");
        asm volatile("barrier.cluster.wait.aligned;"   ::: "memory");

        const uint32_t stageAddr = s2u(&stage[0][0][0]);
        uint32_t rstage[8];
        #pragma unroll
        for (int rk = 0; rk < 8; rk++)
            asm("mapa.shared::cluster.u32 %0, %1, %2;"
                : "=r"(rstage[rk]) : "r"(stageAddr), "r"(rk));

        const int lane = tid & 31;
        const int gbase = lane & ~7;
        const bool leader = ((lane & 7) == 0);
        float cst[CPC];
        #pragma unroll
        for (int j = 0; j < CPC; j++) cst[j] = 0.f;

        const int nIter = (WN + D - 1) / D;

        float zv[CPC];
        #pragma unroll
        for (int j = 0; j < CPC; j++) {
            const int ch = chBase + j;
            const int t = (ch % D);
            zv[j] = (kp == 0 && t < WN)
                  ? Z[(t*BD + ch/D)*1024 + g*HN + U0 + ul] : 0.f;
        }

        for (int it = 0; it < nIter; it++) {
            const int rp = (it + 1) & 1;
            const int wp = it & 1;

            #pragma unroll
            for (int j = 0; j < CPC; j++) {
                const int ch  = chBase + j;
                const int row = ch / D;
                const int t   = it*D + (ch % D);
                const ulonglong2* hp = (const ulonglong2*)&stage[rp][j][kp*128];
                unsigned long long p0a=0ull, p0b=0ull, p1a=0ull, p1b=0ull;
                #pragma unroll
                for (int i = 0; i < 32; i += 2) {
                    ulonglong2 h0 = hp[i];
                    ulonglong2 h1 = hp[i+1];
                    asm("fma.rn.f32x2 %0, %1, %2, %0;" : "+l"(p0a) : "l"(w[i].x),   "l"(h0.x));
                    asm("fma.rn.f32x2 %0, %1, %2, %0;" : "+l"(p1a) : "l"(w[i].y),   "l"(h0.y));
                    asm("fma.rn.f32x2 %0, %1, %2, %0;" : "+l"(p0b) : "l"(w[i+1].x), "l"(h1.x));
                    asm("fma.rn.f32x2 %0, %1, %2, %0;" : "+l"(p1b) : "l"(w[i+1].y), "l"(h1.y));
                }
                float v = __uint_as_float((unsigned)p0a) + __uint_as_float((unsigned)(p0a>>32))
                        + __uint_as_float((unsigned)p0b) + __uint_as_float((unsigned)(p0b>>32))
                        + __uint_as_float((unsigned)p1a) + __uint_as_float((unsigned)(p1a>>32))
                        + __uint_as_float((unsigned)p1b) + __uint_as_float((unsigned)(p1b>>32));
                v += __shfl_xor_sync(0xffffffffu, v, 1);
                if (kp == 0) v += zv[j];
                float zi = __shfl_sync(0xffffffffu, v, gbase + 0);
                float zf = __shfl_sync(0xffffffffu, v, gbase + 2);
                float zg = __shfl_sync(0xffffffffu, v, gbase + 4);
                float zo = __shfl_sync(0xffffffffu, v, gbase + 6);
                if (leader && t < WN) {
                    float ig = fast_sigmoid(zi);
                    float fg = fast_sigmoid(zf);
                    float og = fast_sigmoid(zo);
                    float cn = fg*cst[j] + ig*fast_tanh(zg);
                    cst[j] = cn;
                    float hn = og*fast_tanh(cn);
                    h[(t*BD + row)*HN + U0 + ul] = hn;
                    uint32_t off = ((wp*CPC + j)*256 + U0 + ul)*4;
                    unsigned hu = __float_as_uint(hn);
                    #pragma unroll
                    for (int rk = 0; rk < 8; rk++)
                        asm volatile("st.shared::cluster.b32 [%0], %1;"
                                     :: "r"(rstage[rk] + off), "r"(hu) : "memory");
                }
            }

            asm volatile("barrier.cluster.arrive.aligned;" ::: "memory");

            #pragma unroll
            for (int j = 0; j < CPC; j++) {
                const int ch = chBase + j;
                const int t = (it+1)*D + (ch % D);
                zv[j] = (kp == 0 && t < WN && it+1 < nIter)
                      ? Z[(t*BD + ch/D)*1024 + g*HN + U0 + ul] : 0.f;
            }

            asm volatile("barrier.cluster.wait.aligned;" ::: "memory");

            // coarse publish: every PUBK intervals + final. All leaders' h
            // stores for intervals <= it happen-before here (cluster barrier);
            // one gpu-scope fence raises them to gpu visibility.
            if ((((it+1) & (PUBK-1)) == 0 || it+1 == nIter)
                && rank == 0 && tid == 0) {
                asm volatile("fence.acq_rel.gpu;" ::: "memory");
                asm volatile("st.relaxed.gpu.global.u32 [%0], %1;"
                             :: "l"(&g_prog[progSlot*16 + clIdx]),
                                "r"((unsigned)(it+1)) : "memory");
            }
        }
        return;
    }

    // ========================= consumer GEMM path ===========================
    const int nG   = (int)gridDim.x - NCL*8;
    const int gIdx = (int)blockIdx.x - NCL*8;
    const int MT = (M + 127)/128, NT = N/128;
    const int tx = tid & 15, ty = tid >> 4;
    const int lrow = tid >> 1;
    const int lhalf = (tid & 1) * 4;

    for (int tau = gIdx; tau < MT*NT; tau += nG) {
        const int mt = tau / NT, nt = tau % NT;
        // wait until all rec clusters have covered this tile's A rows
        {
            int lastRow = mt*128 + 127; if (lastRow > M-1) lastRow = M-1;
            unsigned target = (unsigned)((lastRow / BD) / D + 1);
            for (int cl = 0; cl < NCL; cl++) {
                const unsigned* pp = &g_prog[progSlot*16 + cl];
                unsigned v;
                while (true) {
                    asm volatile("ld.acquire.gpu.global.u32 %0, [%1];"
                                 : "=r"(v) : "l"(pp) : "memory");
                    if (v >= target) break;
                    __nanosleep(512);
                }
            }
        }
        const int mBase = mt*128, nBase = nt*128;
        float acc[8][8] = {};
        for (int k0 = 0; k0 < K; k0 += 8) {
            {
                int m = mBase + lrow;
                float4 v = make_float4(0.f,0.f,0.f,0.f);
                if (m < M) {
                    v = *(const float4*)&Agm[m*K + k0 + lhalf];
                    if (RES) {
                        float4 rv = *(const float4*)&Rgm[m*K + k0 + lhalf];
                        v.x += rv.x; v.y += rv.y; v.z += rv.z; v.w += rv.w;
                    }
                }
                As[lhalf+0][lrow] = v.x; As[lhalf+1][lrow] = v.y;
                As[lhalf+2][lrow] = v.z; As[lhalf+3][lrow] = v.w;
                int n = nBase + lrow;
                float4 wv = (n < N) ? *(const float4*)&Bgm[n*K + k0 + lhalf]
                                    : make_float4(0.f,0.f,0.f,0.f);
                Bs[lhalf+0][lrow] = wv.x; Bs[lhalf+1][lrow] = wv.y;
                Bs[lhalf+2][lrow] = wv.z; Bs[lhalf+3][lrow] = wv.w;
            }
            __syncthreads();
            #pragma unroll
            for (int kk = 0; kk < 8; kk++) {
                float a[8], b[8];
                *(float4*)&a[0] = *(const float4*)&As[kk][ty*8];
                *(float4*)&a[4] = *(const float4*)&As[kk][ty*8+4];
                *(float4*)&b[0] = *(const float4*)&Bs[kk][tx*8];
                *(float4*)&b[4] = *(const float4*)&Bs[kk][tx*8+4];
                #pragma unroll
                for (int i = 0; i < 8; i++)
                    #pragma unroll
                    for (int j = 0; j < 8; j++)
                        acc[i][j] = fmaf(a[i], b[j], acc[i][j]);
            }
            __syncthreads();
        }
        #pragma unroll
        for (int i = 0; i < 8; i++) {
            int m = mBase + ty*8 + i;
            if (m >= M) continue;
            #pragma unroll
            for (int j = 0; j < 8; j++) {
                int n = nBase + tx*8 + j;
                if (n >= N) continue;
                float v = acc[i][j] + bias[n];
                if (ACT == 1) v = tanhf(v);
                Cgm[m*N + n] = v;
            }
        }
    }
}

// ---------------- assemble all six outputs ----------------------------------
__global__ void outputs_kernel(const float* __restrict__ x,
                               const float* __restrict__ val,
                               float* __restrict__ out, int out_size)
{
    for (int idx = blockIdx.x*blockDim.x + threadIdx.x; idx < out_size;
         idx += gridDim.x*blockDim.x)
    {
        float v = 0.f;
        if (idx < P0) {                              // prediction_values
            int w = idx / 3584; int rem = idx - w*3584;
            int b = rem / 28;   int j = rem - b*28;
            v = g_rnn[(w*BD + (b % BD))*OUTN + j];
        } else if (idx < P1) {                       // actual_values
            int i = idx - P0;
            int wo = i / 3584; int rem = i - wo*3584;
            int b = rem / 28;  int j = rem - b*28;
            int tt = 28 + wo + j;
            v = x[b*TLEN + tt] / g_Sfull[b*307 + tt] / g_levels[b*TLEN + 27 + wo];
        } else if (idx < P2) {                       // holdout_prediction
            int i = idx - P1;
            int b = i / 28; int j = i - b*28;
            int k = 286 + j; if (k >= 307) k -= 7;
            float hh = g_rnn[(272*BD + (b % BD))*OUTN + j]
                       * g_Sfull[b*307 + k] * g_levels[b*TLEN + 299];
            v = hh > 0.f ? hh : 0.f;
        } else if (idx < P3) {                       // rnn_out
            int i = idx - P2;
            int w = i / 3584; int rem = i - w*3584;
            int b = rem / 28; int j = rem - b*28;
            v = g_rnn[(w*BD + (b % BD))*OUTN + j];
        } else if (idx < P4) {                       // hav
            v = val[idx - P3];
        } else if (idx < P5) {                       // hav_norm
            int i = idx - P4;
            int b = i / 28; int j = i - b*28;
            int k = 286 + j; if (k >= 307) k -= 7;
            v = val[b*28 + j] / g_Sfull[b*307 + k] / g_levels[b*TLEN + 299];
        }
        out[idx] = v;
    }
}

// ---------------- host launcher ----------------------------------------------
extern "C" void kernel_launch(void* const* d_in, const int* in_sizes, int n_in,
                              void* d_out, int out_size)
{
    const float* x      = (const float*)d_in[0];
    const float* val    = (const float*)d_in[1];
    const float* alpha  = (const float*)d_in[2];
    const float* gamma  = (const float*)d_in[3];
    const float* iseas  = (const float*)d_in[4];
    const float* cats   = (const float*)d_in[5];
    const float* myp    = (const float*)d_in[6];
    const float* Wih1   = (const float*)d_in[7];
    const float* Whh1   = (const float*)d_in[8];
    const float* b1     = (const float*)d_in[9];
    const float* Wih2   = (const float*)d_in[10];
    const float* Whh2   = (const float*)d_in[11];
    const float* b2     = (const float*)d_in[12];
    const float* Wih3   = (const float*)d_in[13];
    const float* Whh3   = (const float*)d_in[14];
    const float* b3     = (const float*)d_in[15];
    const float* Wih4   = (const float*)d_in[16];
    const float* Whh4   = (const float*)d_in[17];
    const float* b4     = (const float*)d_in[18];
    const float* lW     = (const float*)d_in[19];
    const float* lb     = (const float*)d_in[20];
    const float* sW     = (const float*)d_in[21];
    const float* sb     = (const float*)d_in[22];

    float *pWin, *pZ, *pZ2, *pHA, *pHB, *pRnn;
    cudaGetSymbolAddress((void**)&pWin, g_win);
    cudaGetSymbolAddress((void**)&pZ,   g_Z);
    cudaGetSymbolAddress((void**)&pZ2,  g_Z2);
    cudaGetSymbolAddress((void**)&pHA,  g_hA);
    cudaGetSymbolAddress((void**)&pHB,  g_hB);
    cudaGetSymbolAddress((void**)&pRnn, g_rnn);

    // 1) exponential smoothing + seasonals (+ progress reset)
    es_kernel<<<1, 128>>>(x, alpha, gamma, iseas);

    // 2) normalized window inputs
    build_win<<<(MROWS*FIN + 255)/256, 256>>>(x, cats, myp);

    // 3) layer-1 input GEMM (K=49) -> Z_A
    sgemm_nt<0><<<dim3(16, (MROWS+63)/64), 256>>>(pWin, Wih1, b1, pZ, MROWS, 1024, FIN);

    // 4) fused pipeline: rec(L) || input-GEMM(L+1) consuming h(L) progressively
    // fused1: rec1 (Z_A -> hA) || gemm2 (hA @ Wih2 -> Z_B)
    fused_rec_gemm<1,1,10,0,0><<<144, 256>>>(
        pZ, Whh1, pHA, pHA, nullptr, Wih2, b2, pZ2, MROWS, 1024, HN, 0);

    // fused2: rec2 (Z_B -> hB) || gemm3 (hB @ Wih3 -> Z_A)
    fused_rec_gemm<2,2,10,0,0><<<144, 256>>>(
        pZ2, Whh2, pHB, pHB, nullptr, Wih3, b3, pZ, MROWS, 1024, HN, 1);

    // fused3: rec3 (Z_A -> hA) || gemm4 (hA @ Wih4 -> Z_B)
    fused_rec_gemm<2,2,10,0,0><<<144, 256>>>(
        pZ, Whh3, pHA, pHA, nullptr, Wih4, b4, pZ2, MROWS, 1024, HN, 2);

    // fused4: rec4 (Z_B -> hA) || linear: tanh((hA+hB) @ lW^T + lb) -> Z_A
    fused_rec_gemm<4,6,15,1,1><<<144, 256>>>(
        pZ2, Whh4, pHA, pHA, pHB, lW, lb, pZ, MROWS, HN, HN, 3);

    // 5) score
    sgemm_nt<0><<<dim3(1, (MROWS+63)/64), 256>>>(pZ, sW, sb, pRnn, MROWS, OUTN, HN);

    // 6) outputs
    outputs_kernel<<<1024, 256>>>(x, val, (float*)d_out, out_size);
}

// round 13
// speedup vs baseline: 1.1502x; 1.1186x over previous
#include <cuda_runtime.h>
#include <math.h>
#include <stdint.h>

// ---------------- problem constants ----------------
#define BATCH 128
#define TLEN  300
#define LW    28
#define OUTN  28
#define SPN   7
#define EN    20
#define HN    256
#define WN    273          // T - L + 1
#define WOUT  245          // W - OUT
#define FIN   49           // L + 1 + E
#define BD    10           // distinct batch rows (b % 10)
#define MROWS (WN*BD)      // 2730

// output region boundaries (float32 elements, tuple order)
#define P0 878080          // prediction_values (245,128,28)
#define P1 1756160         // actual_values    (245,128,28)
#define P2 1759744         // holdout_prediction (128,28)
#define P3 2738176         // rnn_out (273,128,28)
#define P4 2741760         // hav (128,28)
#define P5 2745344         // hav_norm (128,28)

// ---------------- device scratch (no cudaMalloc allowed) ----------------
__device__ float g_Sfull[BATCH*307];
__device__ float g_levels[BATCH*TLEN];
__device__ float g_win[MROWS*FIN];
__device__ float g_Z[MROWS*1024];
__device__ float g_hA[MROWS*HN];
__device__ float g_hB[MROWS*HN];
__device__ float g_rnn[MROWS*OUTN];

// ---------------- helpers ----------------
__device__ __forceinline__ uint32_t s2u(const void* p){
    uint32_t a;
    asm("{ .reg .u64 t; cvta.to.shared.u64 t, %1; cvt.u32.u64 %0, t; }"
        : "=r"(a) : "l"(p));
    return a;
}
__device__ __forceinline__ float fast_sigmoid(float z){
    return __fdividef(1.f, 1.f + __expf(-z));
}
__device__ __forceinline__ float fast_tanh(float x){
    float a = fminf(fmaxf(x, -15.f), 15.f);
    float e = __expf(2.f*a);
    return __fdividef(e - 1.f, e + 1.f);
}

// ---------------- ES (Holt-Winters) smoothing ----------------
__global__ void es_kernel(const float* __restrict__ x,
                          const float* __restrict__ alpha_raw,
                          const float* __restrict__ gamma_raw,
                          const float* __restrict__ init_seas)
{
    __shared__ float ring[BATCH*SPN];
    int b = threadIdx.x;
    if (b >= BATCH) return;
    float a = fast_sigmoid(alpha_raw[b]);
    float g = fast_sigmoid(gamma_raw[b]);
    float s0 = 0.f;
    for (int k = 0; k < SPN; k++) {
        float s = __expf(init_seas[b*SPN + k]);
        g_Sfull[b*307 + k] = s;
        ring[b*SPN + k] = s;
        if (k == 0) s0 = s;
    }
    g_Sfull[b*307 + 7] = s0;
    float level = __fdividef(x[b*TLEN], s0);
    g_levels[b*TLEN] = level;
    for (int t = 1; t < TLEN; t++) {
        float xt = x[b*TLEN + t];
        int slot = t % SPN;
        float s = ring[b*SPN + slot];
        float lvl  = a*__fdividef(xt, s)   + (1.f - a)*level;
        float snew = g*__fdividef(xt, lvl) + (1.f - g)*s;
        ring[b*SPN + slot] = snew;
        g_Sfull[b*307 + t + 7] = snew;
        level = lvl;
        g_levels[b*TLEN + t] = lvl;
    }
}

// ---------------- build window_input (10 distinct batch rows) ----------
__global__ void build_win(const float* __restrict__ x,
                          const float* __restrict__ cats,
                          const float* __restrict__ myp)
{
    int idx = blockIdx.x*blockDim.x + threadIdx.x;
    if (idx >= MROWS*FIN) return;
    int f  = idx % FIN;
    int r  = idx / FIN;
    int bb = r % BD;
    int w  = r / BD;
    float v;
    if (f < LW) {
        int tt = w + f;
        v = __fdividef(__fdividef(x[bb*TLEN + tt], g_Sfull[bb*307 + tt]),
                       g_levels[bb*TLEN + 27 + w]);
    } else if (f < LW + EN) {
        v = cats[bb*EN + (f - LW)];
    } else {
        v = myp[0];
    }
    g_win[idx] = v;
}

// ---------------- generic SGEMM-NT (64x64; K=49, linear, score) -----------
// RES: adds R (same shape as A) to A on load.
template<int ACT, int RES>
__global__ void sgemm_nt(const float* __restrict__ A,
                         const float* __restrict__ R,
                         const float* __restrict__ Bm,
                         const float* __restrict__ bias,
                         float* __restrict__ C,
                         int M, int N, int K)
{
    __shared__ float As[16][64];
    __shared__ float Bs[16][64];
    const int tid = threadIdx.x;
    const int mBase = blockIdx.y * 64;
    const int nBase = blockIdx.x * 64;
    const int lr = tid >> 2;
    const int lk = (tid & 3) << 2;
    const int tx = tid & 15, ty = tid >> 4;
    float acc[4][4] = {};

    for (int k0 = 0; k0 < K; k0 += 16) {
        {
            const int m = mBase + lr;
            const int n = nBase + lr;
            #pragma unroll
            for (int i = 0; i < 4; i++) {
                int k = k0 + lk + i;
                float av = 0.f;
                if (m < M && k < K) {
                    av = A[m*K + k];
                    if (RES) av += R[m*K + k];
                }
                As[lk+i][lr] = av;
                Bs[lk+i][lr] = (n < N && k < K) ? Bm[n*K + k] : 0.f;
            }
        }
        __syncthreads();
        #pragma unroll
        for (int kk = 0; kk < 16; kk++) {
            const float4 a4 = *(const float4*)&As[kk][ty << 2];
            const float4 b4 = *(const float4*)&Bs[kk][tx << 2];
            float av[4] = {a4.x, a4.y, a4.z, a4.w};
            float bv[4] = {b4.x, b4.y, b4.z, b4.w};
            #pragma unroll
            for (int i = 0; i < 4; i++)
                #pragma unroll
                for (int j = 0; j < 4; j++)
                    acc[i][j] += av[i] * bv[j];
        }
        __syncthreads();
    }

    #pragma unroll
    for (int i = 0; i < 4; i++) {
        int m = mBase + (ty << 2) + i;
        if (m >= M) continue;
        #pragma unroll
        for (int j = 0; j < 4; j++) {
            int n = nBase + (tx << 2) + j;
            if (n >= N) continue;
            float v = acc[i][j] + bias[n];
            if (ACT == 1) v = tanhf(v);
            C[m*N + n] = v;
        }
    }
}

// ------- pipelined SGEMM-NT 128x128, BK=8, 8x8/thread, double-buffered -----
// Register prefetch of the next K-slice overlaps the FMA block; one
// __syncthreads per iteration (WAR across the two SMEM buffers is ordered by
// the sync chain). 2 CTAs/SM.
template<int ACT>
__global__ void __launch_bounds__(256,2)
sgemm128(const float* __restrict__ A,
         const float* __restrict__ Bm,
         const float* __restrict__ bias,
         float* __restrict__ C,
         int M, int N, int K)
{
    __shared__ float As[2][8][132];
    __shared__ float Bs[2][8][132];
    const int tid = threadIdx.x;
    const int mBase = blockIdx.y * 128;
    const int nBase = blockIdx.x * 128;
    const int tx = tid & 15, ty = tid >> 4;
    const int lrow = tid >> 1;
    const int lhalf = (tid & 1) * 4;
    const int mRow = mBase + lrow;
    const int nRow = nBase + lrow;
    float acc[8][8] = {};

    float4 va = make_float4(0.f,0.f,0.f,0.f);
    float4 vb = make_float4(0.f,0.f,0.f,0.f);
    if (mRow < M) va = *(const float4*)&A[mRow*K + lhalf];
    if (nRow < N) vb = *(const float4*)&Bm[nRow*K + lhalf];

    int buf = 0;
    for (int k0 = 0; k0 < K; k0 += 8) {
        As[buf][lhalf+0][lrow] = va.x; As[buf][lhalf+1][lrow] = va.y;
        As[buf][lhalf+2][lrow] = va.z; As[buf][lhalf+3][lrow] = va.w;
        Bs[buf][lhalf+0][lrow] = vb.x; Bs[buf][lhalf+1][lrow] = vb.y;
        Bs[buf][lhalf+2][lrow] = vb.z; Bs[buf][lhalf+3][lrow] = vb.w;
        __syncthreads();

        if (k0 + 8 < K) {   // prefetch next slice (overlaps compute below)
            va = make_float4(0.f,0.f,0.f,0.f);
            vb = make_float4(0.f,0.f,0.f,0.f);
            if (mRow < M) va = *(const float4*)&A[mRow*K + k0 + 8 + lhalf];
            if (nRow < N) vb = *(const float4*)&Bm[nRow*K + k0 + 8 + lhalf];
        }

        #pragma unroll
        for (int kk = 0; kk < 8; kk++) {
            float a[8], b[8];
            *(float4*)&a[0] = *(const float4*)&As[buf][kk][ty*8];
            *(float4*)&a[4] = *(const float4*)&As[buf][kk][ty*8+4];
            *(float4*)&b[0] = *(const float4*)&Bs[buf][kk][tx*8];
            *(float4*)&b[4] = *(const float4*)&Bs[buf][kk][tx*8+4];
            #pragma unroll
            for (int i = 0; i < 8; i++)
                #pragma unroll
                for (int j = 0; j < 8; j++)
                    acc[i][j] = fmaf(a[i], b[j], acc[i][j]);
        }
        buf ^= 1;
    }
    #pragma unroll
    for (int i = 0; i < 8; i++) {
        int m = mBase + ty*8 + i;
        if (m >= M) continue;
        #pragma unroll
        for (int j = 0; j < 8; j++) {
            int n = nBase + tx*8 + j;
            if (n >= N) continue;
            float v = acc[i][j] + bias[n];
            if (ACT == 1) v = tanhf(v);
            C[m*N + n] = v;
        }
    }
}

// ---------------- cluster-per-chain persistent LSTM recurrence --------------
// (round-10 proven version, unchanged)
template<int CPC, int D>
__global__ void __launch_bounds__(256,1) __cluster_dims__(8,1,1)
lstm_chain(const float* __restrict__ Z,
           const float* __restrict__ Whh,
           float* __restrict__ h)
{
    __shared__ __align__(16) float stage[2][CPC][256];  // parity double buffer

    const int tid = threadIdx.x;
    uint32_t rank;
    asm("mov.u32 %0, %%cluster_ctarank;" : "=r"(rank));
    const int U0 = (int)rank * 32;
    const int kp = tid & 1;
    const int g  = (tid >> 1) & 3;
    const int ul = tid >> 3;
    const int chBase = (blockIdx.x >> 3) * CPC;

    ulonglong2 w[32];
    {
        const ulonglong2* w16 =
            (const ulonglong2*)(Whh + (g*HN + U0 + ul)*HN + kp*128);
        #pragma unroll
        for (int i = 0; i < 32; i++) w[i] = w16[i];
    }

    for (int i = tid; i < 2*CPC*256; i += 256) ((float*)stage)[i] = 0.f;
    __syncthreads();
    asm volatile("barrier.cluster.arrive.aligned;" ::: "memory");
    asm volatile("barrier.cluster.wait.aligned;"   ::: "memory");

    const uint32_t stageAddr = s2u(&stage[0][0][0]);
    uint32_t rstage[8];
    #pragma unroll
    for (int rk = 0; rk < 8; rk++)
        asm("mapa.shared::cluster.u32 %0, %1, %2;"
            : "=r"(rstage[rk]) : "r"(stageAddr), "r"(rk));

    const int lane = tid & 31;
    const int gbase = lane & ~7;
    const bool leader = ((lane & 7) == 0);
    float cst[CPC];
    #pragma unroll
    for (int j = 0; j < CPC; j++) cst[j] = 0.f;

    const int nIter = (WN + D - 1) / D;

    float zv[CPC];
    #pragma unroll
    for (int j = 0; j < CPC; j++) {
        const int ch = chBase + j;
        const int t = (ch % D);
        zv[j] = (kp == 0 && t < WN)
              ? Z[(t*BD + ch/D)*1024 + g*HN + U0 + ul] : 0.f;
    }

    for (int it = 0; it < nIter; it++) {
        const int rp = (it + 1) & 1;
        const int wp = it & 1;

        #pragma unroll
        for (int j = 0; j < CPC; j++) {
            const int ch  = chBase + j;
            const int row = ch / D;
            const int t   = it*D + (ch % D);
            const ulonglong2* hp = (const ulonglong2*)&stage[rp][j][kp*128];
            unsigned long long p0a=0ull, p0b=0ull, p1a=0ull, p1b=0ull;
            #pragma unroll
            for (int i = 0; i < 32; i += 2) {
                ulonglong2 h0 = hp[i];
                ulonglong2 h1 = hp[i+1];
                asm("fma.rn.f32x2 %0, %1, %2, %0;" : "+l"(p0a) : "l"(w[i].x),   "l"(h0.x));
                asm("fma.rn.f32x2 %0, %1, %2, %0;" : "+l"(p1a) : "l"(w[i].y),   "l"(h0.y));
                asm("fma.rn.f32x2 %0, %1, %2, %0;" : "+l"(p0b) : "l"(w[i+1].x), "l"(h1.x));
                asm("fma.rn.f32x2 %0, %1, %2, %0;" : "+l"(p1b) : "l"(w[i+1].y), "l"(h1.y));
            }
            float v = __uint_as_float((unsigned)p0a) + __uint_as_float((unsigned)(p0a>>32))
                    + __uint_as_float((unsigned)p0b) + __uint_as_float((unsigned)(p0b>>32))
                    + __uint_as_float((unsigned)p1a) + __uint_as_float((unsigned)(p1a>>32))
                    + __uint_as_float((unsigned)p1b) + __uint_as_float((unsigned)(p1b>>32));
            v += __shfl_xor_sync(0xffffffffu, v, 1);
            if (kp == 0) v += zv[j];
            float zi = __shfl_sync(0xffffffffu, v, gbase + 0);
            float zf = __shfl_sync(0xffffffffu, v, gbase + 2);
            float zg = __shfl_sync(0xffffffffu, v, gbase + 4);
            float zo = __shfl_sync(0xffffffffu, v, gbase + 6);
            if (leader && t < WN) {
                float ig = fast_sigmoid(zi);
                float fg = fast_sigmoid(zf);
                float og = fast_sigmoid(zo);
                float cn = fg*cst[j] + ig*fast_tanh(zg);
                cst[j] = cn;
                float hn = og*fast_tanh(cn);
                h[(t*BD + row)*HN + U0 + ul] = hn;
                uint32_t off = ((wp*CPC + j)*256 + U0 + ul)*4;
                unsigned hu = __float_as_uint(hn);
                #pragma unroll
                for (int rk = 0; rk < 8; rk++)
                    asm volatile("st.shared::cluster.b32 [%0], %1;"
                                 :: "r"(rstage[rk] + off), "r"(hu) : "memory");
            }
        }

        asm volatile("barrier.cluster.arrive.aligned;" ::: "memory");

        #pragma unroll
        for (int j = 0; j < CPC; j++) {
            const int ch = chBase + j;
            const int t = (it+1)*D + (ch % D);
            zv[j] = (kp == 0 && t < WN && it+1 < nIter)
                  ? Z[(t*BD + ch/D)*1024 + g*HN + U0 + ul] : 0.f;
        }

        asm volatile("barrier.cluster.wait.aligned;" ::: "memory");
    }
}

// ---------------- assemble all six outputs ----------------------------------
__global__ void outputs_kernel(const float* __restrict__ x,
                               const float* __restrict__ val,
                               float* __restrict__ out, int out_size)
{
    for (int idx = blockIdx.x*blockDim.x + threadIdx.x; idx < out_size;
         idx += gridDim.x*blockDim.x)
    {
        float v = 0.f;
        if (idx < P0) {                              // prediction_values
            int w = idx / 3584; int rem = idx - w*3584;
            int b = rem / 28;   int j = rem - b*28;
            v = g_rnn[(w*BD + (b % BD))*OUTN + j];
        } else if (idx < P1) {                       // actual_values
            int i = idx - P0;
            int wo = i / 3584; int rem = i - wo*3584;
            int b = rem / 28;  int j = rem - b*28;
            int tt = 28 + wo + j;
            v = __fdividef(__fdividef(x[b*TLEN + tt], g_Sfull[b*307 + tt]),
                           g_levels[b*TLEN + 27 + wo]);
        } else if (idx < P2) {                       // holdout_prediction
            int i = idx - P1;
            int b = i / 28; int j = i - b*28;
            int k = 286 + j; if (k >= 307) k -= 7;
            float hh = g_rnn[(272*BD + (b % BD))*OUTN + j]
                       * g_Sfull[b*307 + k] * g_levels[b*TLEN + 299];
            v = hh > 0.f ? hh : 0.f;
        } else if (idx < P3) {                       // rnn_out
            int i = idx - P2;
            int w = i / 3584; int rem = i - w*3584;
            int b = rem / 28; int j = rem - b*28;
            v = g_rnn[(w*BD + (b % BD))*OUTN + j];
        } else if (idx < P4) {                       // hav
            v = val[idx - P3];
        } else if (idx < P5) {                       // hav_norm
            int i = idx - P4;
            int b = i / 28; int j = i - b*28;
            int k = 286 + j; if (k >= 307) k -= 7;
            v = __fdividef(__fdividef(val[b*28 + j], g_Sfull[b*307 + k]),
                           g_levels[b*TLEN + 299]);
        }
        out[idx] = v;
    }
}

// ---------------- host launcher ----------------------------------------------
extern "C" void kernel_launch(void* const* d_in, const int* in_sizes, int n_in,
                              void* d_out, int out_size)
{
    const float* x      = (const float*)d_in[0];
    const float* val    = (const float*)d_in[1];
    const float* alpha  = (const float*)d_in[2];
    const float* gamma  = (const float*)d_in[3];
    const float* iseas  = (const float*)d_in[4];
    const float* cats   = (const float*)d_in[5];
    const float* myp    = (const float*)d_in[6];
    const float* Wih1   = (const float*)d_in[7];
    const float* Whh1   = (const float*)d_in[8];
    const float* b1     = (const float*)d_in[9];
    const float* Wih2   = (const float*)d_in[10];
    const float* Whh2   = (const float*)d_in[11];
    const float* b2     = (const float*)d_in[12];
    const float* Wih3   = (const float*)d_in[13];
    const float* Whh3   = (const float*)d_in[14];
    const float* b3     = (const float*)d_in[15];
    const float* Wih4   = (const float*)d_in[16];
    const float* Whh4   = (const float*)d_in[17];
    const float* b4     = (const float*)d_in[18];
    const float* lW     = (const float*)d_in[19];
    const float* lb     = (const float*)d_in[20];
    const float* sW     = (const float*)d_in[21];
    const float* sb     = (const float*)d_in[22];

    float *pWin, *pZ, *pHA, *pHB, *pRnn;
    cudaGetSymbolAddress((void**)&pWin, g_win);
    cudaGetSymbolAddress((void**)&pZ,   g_Z);
    cudaGetSymbolAddress((void**)&pHA,  g_hA);
    cudaGetSymbolAddress((void**)&pHB,  g_hB);
    cudaGetSymbolAddress((void**)&pRnn, g_rnn);

    // 1) exponential smoothing + seasonals
    es_kernel<<<1, 128>>>(x, alpha, gamma, iseas);

    // 2) normalized window inputs (batch collapsed to 10 distinct rows)
    build_win<<<(MROWS*FIN + 255)/256, 256>>>(x, cats, myp);

    dim3 gBig128(8, (MROWS + 127)/128);   // N=1024, K=256 GEMMs

    // ---- layer 1 (d=1): K=49 input GEMM, then 10 clusters x 1 chain ----
    sgemm_nt<0,0><<<dim3(16, (MROWS+63)/64), 256>>>(
        pWin, nullptr, Wih1, b1, pZ, MROWS, 1024, FIN);
    lstm_chain<1,1><<<80, 256>>>(pZ, Whh1, pHA);

    // ---- layer 2 (d=2): -> hB (kept for residual) ----
    sgemm128<0><<<gBig128, 256>>>(pHA, Wih2, b2, pZ, MROWS, 1024, HN);
    lstm_chain<2,2><<<80, 256>>>(pZ, Whh2, pHB);

    // ---- layer 3 (d=2) ----
    sgemm128<0><<<gBig128, 256>>>(pHB, Wih3, b3, pZ, MROWS, 1024, HN);
    lstm_chain<2,2><<<80, 256>>>(pZ, Whh3, pHA);

    // ---- layer 4 (d=6): 15 clusters x 4 chains ----
    sgemm128<0><<<gBig128, 256>>>(pHA, Wih4, b4, pZ, MROWS, 1024, HN);
    lstm_chain<4,6><<<120, 256>>>(pZ, Whh4, pHA);

    // ---- linear + tanh with fused residual (hA + hB) -> g_Z (64x64 tiles) --
    sgemm_nt<1,1><<<dim3(4, (MROWS+63)/64), 256>>>(
        pHA, pHB, lW, lb, pZ, MROWS, HN, HN);

    // ---- score ----
    sgemm_nt<0,0><<<dim3(1, (MROWS+63)/64), 256>>>(
        pZ, nullptr, sW, sb, pRnn, MROWS, OUTN, HN);

    // ---- assemble outputs ----
    outputs_kernel<<<1024, 256>>>(x, val, (float*)d_out, out_size);
}